// round 4
// baseline (speedup 1.0000x reference)
#include <cuda_runtime.h>
#include <cstdint>

// SoftReordering: B=16, S=1024, E=1024, W=7, PAD_VAL=0
//   logits[b,t,v] = sum_{w,e} x[b,t+w-3,e] * weight[t, v, w*E+e]   (+bias[t,v])
//   gates = sigmoid(logits)
//   out[b,t,e]   = tanh( sum_w gates[b,t,w] * x[b,t+w-3,e] )
//
// One CTA per t. 4 warps; warp r owns batches 4r..4r+3, lanes stride e by
// float4. Packed fma.rn.f32x2 halves FP32 FMA issue (FFMA 3-reg is rt=2/SMSP
// on sm_103a). Consecutive CTAs (consecutive t) share 6/7 x rows via L2.

#define BB 16
#define SS 1024
#define EE 1024
#define WW 7
#define HWD 3
#define WE (WW * EE)   // 7168

__device__ __forceinline__ void ffma2(unsigned long long& d,
                                      unsigned long long a,
                                      unsigned long long b) {
    asm("fma.rn.f32x2 %0, %1, %2, %3;" : "=l"(d) : "l"(a), "l"(b), "l"(d));
}

__device__ __forceinline__ float2 unpack2(unsigned long long v) {
    float2 r;
    asm("mov.b64 {%0, %1}, %2;" : "=f"(r.x), "=f"(r.y) : "l"(v));
    return r;
}

__device__ __forceinline__ unsigned long long pack_dup(float g) {
    unsigned long long p;
    asm("mov.b64 %0, {%1, %1};" : "=l"(p) : "f"(g));
    return p;
}

__device__ __forceinline__ float tanh_ap(float x) {
    float r;
    asm("tanh.approx.f32 %0, %1;" : "=f"(r) : "f"(x));
    return r;
}

__global__ void __launch_bounds__(128, 4)
soft_reorder_kernel(const float* __restrict__ x,
                    const float* __restrict__ wgt,
                    const float* __restrict__ bias,
                    float* __restrict__ out) {
    const int t    = blockIdx.x;
    const int warp = threadIdx.x >> 5;
    const int lane = threadIdx.x & 31;
    const int b0   = warp << 2;           // first batch of this warp

    __shared__ float s_gates[BB][8];

    // valid window taps: rows t+w-3 in [0, S)
    const int wlo = (t < HWD) ? (HWD - t) : 0;
    const int whi = (t + HWD >= SS) ? (SS + HWD - t) : WW;   // exclusive

    // ------------------------------------------------------------------
    // Step 1: logits accumulation.  acc[bb][v] holds packed (even,odd) sums.
    // ------------------------------------------------------------------
    unsigned long long acc[4][7];
#pragma unroll
    for (int bb = 0; bb < 4; ++bb)
#pragma unroll
        for (int v = 0; v < 7; ++v)
            acc[bb][v] = 0ull;

    const float* wt = wgt + (size_t)t * (WW * WE);   // weight[t]
    const int ebyte0 = lane * 4;                     // e start (floats) per lane

    for (int w = wlo; w < whi; ++w) {
        const int row = t + w - HWD;
        const float* xr = x + ((size_t)b0 * SS + row) * EE;
        const float* wr = wt + w * EE;
        for (int c = 0; c < 8; ++c) {
            const int e = c * 128 + ebyte0;
            ulonglong2 xv[4];
#pragma unroll
            for (int bb = 0; bb < 4; ++bb)
                xv[bb] = *reinterpret_cast<const ulonglong2*>(
                    xr + (size_t)bb * SS * EE + e);
#pragma unroll
            for (int v = 0; v < 7; ++v) {
                const ulonglong2 wv = *reinterpret_cast<const ulonglong2*>(
                    wr + (size_t)v * WE + e);
#pragma unroll
                for (int bb = 0; bb < 4; ++bb) {
                    ffma2(acc[bb][v], xv[bb].x, wv.x);
                    ffma2(acc[bb][v], xv[bb].y, wv.y);
                }
            }
        }
    }

    // horizontal: packed halves, then warp butterfly
    float r[4][7];
#pragma unroll
    for (int bb = 0; bb < 4; ++bb)
#pragma unroll
        for (int v = 0; v < 7; ++v) {
            const float2 p = unpack2(acc[bb][v]);
            r[bb][v] = p.x + p.y;
        }
#pragma unroll
    for (int off = 16; off > 0; off >>= 1)
#pragma unroll
        for (int bb = 0; bb < 4; ++bb)
#pragma unroll
            for (int v = 0; v < 7; ++v)
                r[bb][v] += __shfl_xor_sync(0xffffffffu, r[bb][v], off);

    if (lane == 0) {
#pragma unroll
        for (int v = 0; v < 7; ++v) {
            const float bv = bias[t * WW + v];
#pragma unroll
            for (int bb = 0; bb < 4; ++bb) {
                const float z = r[bb][v] + bv;
                s_gates[b0 + bb][v] = 1.0f / (1.0f + __expf(-z));
            }
        }
    }
    __syncthreads();

    // ------------------------------------------------------------------
    // Step 2: out[b,t,e] = tanh( sum_w g[b][w] * x[b,t+w-3,e] )
    // ------------------------------------------------------------------
    unsigned long long gg[4][7];
#pragma unroll
    for (int bb = 0; bb < 4; ++bb)
#pragma unroll
        for (int v = 0; v < 7; ++v)
            gg[bb][v] = pack_dup(s_gates[b0 + bb][v]);

    for (int c = 0; c < 8; ++c) {
        const int e = c * 128 + ebyte0;
#pragma unroll
        for (int bb = 0; bb < 4; ++bb) {
            const float* xb = x + (size_t)(b0 + bb) * SS * EE + e;
            unsigned long long o0 = 0ull, o1 = 0ull;
#pragma unroll
            for (int w = 0; w < WW; ++w) {   // compile-time w -> no reg indexing
                if (w >= wlo && w < whi) {
                    const int row = t + w - HWD;
                    const ulonglong2 xv = *reinterpret_cast<const ulonglong2*>(
                        xb + (size_t)row * EE);
                    ffma2(o0, gg[bb][w], xv.x);
                    ffma2(o1, gg[bb][w], xv.y);
                }
            }
            const float2 p0 = unpack2(o0);
            const float2 p1 = unpack2(o1);
            float4 ov;
            ov.x = tanh_ap(p0.x);
            ov.y = tanh_ap(p0.y);
            ov.z = tanh_ap(p1.x);
            ov.w = tanh_ap(p1.y);
            *reinterpret_cast<float4*>(
                out + ((size_t)(b0 + bb) * SS + t) * EE + e) = ov;
        }
    }
}

extern "C" void kernel_launch(void* const* d_in, const int* in_sizes, int n_in,
                              void* d_out, int out_size) {
    const float* x    = (const float*)d_in[0];
    const float* wgt  = (const float*)d_in[1];
    const float* bias = (const float*)d_in[2];
    float* out        = (float*)d_out;
    soft_reorder_kernel<<<SS, 128>>>(x, wgt, bias, out);
}

// round 6
// speedup vs baseline: 1.2169x; 1.2169x over previous
#include <cuda_runtime.h>
#include <cstdint>

// SoftReordering: B=16, S=1024, E=1024, W=7, PAD_VAL=0
//   logits[b,t,v] = sum_{w,e} x[b,t+w-3,e] * weight[t, v, w*E+e]   (+bias[t,v])
//   gates = sigmoid(logits)
//   out[b,t,e]   = tanh( sum_w gates[b,t,w] * x[b,t+w-3,e] )
//
// R4: weight[t] is the cold-DRAM stream (unique per CTA). Stage it through
// shared memory with cp.async.cg double-buffered per w-slab (7v x 4KB = 28KB),
// so compute never waits on a cold weight LDG. x stays as front-batched LDG
// (L2-warm via 6/7 window overlap between consecutive CTAs).

#define BB 16
#define SS 1024
#define EE 1024
#define WW 7
#define HWD 3
#define WE (WW * EE)            // 7168
#define WBUF_FLOATS (WW * EE)   // one slab: 7 v-rows x 1024 e = 28KB
#define SMEM_BYTES (2 * WBUF_FLOATS * 4 + BB * 8 * 4)

__device__ __forceinline__ uint32_t smem_u32(const void* p) {
    uint32_t a;
    asm("{ .reg .u64 t; cvta.to.shared.u64 t, %1; cvt.u32.u64 %0, t; }"
        : "=r"(a) : "l"(p));
    return a;
}
__device__ __forceinline__ void cp_async16(uint32_t saddr, const void* gptr) {
    asm volatile("cp.async.cg.shared.global [%0], [%1], 16;"
                 :: "r"(saddr), "l"(gptr));
}
__device__ __forceinline__ void cp_commit() {
    asm volatile("cp.async.commit_group;");
}
template <int N>
__device__ __forceinline__ void cp_wait() {
    asm volatile("cp.async.wait_group %0;" :: "n"(N));
}

__device__ __forceinline__ void ffma2(unsigned long long& d,
                                      unsigned long long a,
                                      unsigned long long b) {
    asm("fma.rn.f32x2 %0, %1, %2, %3;" : "=l"(d) : "l"(a), "l"(b), "l"(d));
}
__device__ __forceinline__ float2 unpack2(unsigned long long v) {
    float2 r;
    asm("mov.b64 {%0, %1}, %2;" : "=f"(r.x), "=f"(r.y) : "l"(v));
    return r;
}
__device__ __forceinline__ unsigned long long pack_dup(float g) {
    unsigned long long p;
    asm("mov.b64 %0, {%1, %1};" : "=l"(p) : "f"(g));
    return p;
}
__device__ __forceinline__ float tanh_ap(float x) {
    float r;
    asm("tanh.approx.f32 %0, %1;" : "=f"(r) : "f"(x));
    return r;
}

__global__ void __launch_bounds__(128, 4)
soft_reorder_kernel(const float* __restrict__ x,
                    const float* __restrict__ wgt,
                    const float* __restrict__ bias,
                    float* __restrict__ out) {
    extern __shared__ float smem[];          // [2][7][1024] wbuf + [16][8] gates
    float* s_gates = smem + 2 * WBUF_FLOATS;

    const int t    = blockIdx.x;
    const int tid  = threadIdx.x;
    const int warp = tid >> 5;
    const int lane = tid & 31;
    const int b0   = warp << 2;              // first batch of this warp

    const int wlo = (t < HWD) ? (HWD - t) : 0;
    const int whi = (t + HWD >= SS) ? (SS + HWD - t) : WW;   // exclusive

    const float* wt = wgt + (size_t)t * (WW * WE);           // weight[t]
    const uint32_t sbase = smem_u32(smem);

    // ---- weight slab staging: slab w = weight[t, v, w*E .. w*E+E) for all v
    // 1792 float4 per slab, 14 per thread.
    auto stage = [&](int w, int buf) {
        const uint32_t dst0 = sbase + (uint32_t)buf * (WBUF_FLOATS * 4);
        const float* src0 = wt + w * EE;
#pragma unroll
        for (int k = 0; k < 14; ++k) {
            const int j   = tid + (k << 7);      // 0..1791
            const int v   = j >> 8;              // 0..6
            const int off = (j & 255) << 2;      // float offset in row
            cp_async16(dst0 + (uint32_t)(v * EE + off) * 4,
                       src0 + (size_t)v * WE + off);
        }
        cp_commit();
    };

    // ------------------------------------------------------------------
    // Step 1: logits accumulation, weight from smem (double-buffered).
    // ------------------------------------------------------------------
    unsigned long long acc[4][7];
#pragma unroll
    for (int bb = 0; bb < 4; ++bb)
#pragma unroll
        for (int v = 0; v < 7; ++v)
            acc[bb][v] = 0ull;

    const int e0 = lane << 2;                // lane's float offset within 128-chunk

    stage(0, 0);
    for (int w = 0; w < WW; ++w) {
        if (w + 1 < WW) { stage(w + 1, (w + 1) & 1); cp_wait<1>(); }
        else            { cp_wait<0>(); }
        __syncthreads();

        if (w >= wlo && w < whi) {
            const int row = t + w - HWD;
            const float* xr = x + ((size_t)b0 * SS + row) * EE;
            const float* wb = smem + (w & 1) * WBUF_FLOATS;
#pragma unroll
            for (int c = 0; c < 8; ++c) {
                const int e = (c << 7) + e0;
                ulonglong2 xv[4];
#pragma unroll
                for (int bb = 0; bb < 4; ++bb)
                    xv[bb] = *reinterpret_cast<const ulonglong2*>(
                        xr + (size_t)bb * SS * EE + e);
#pragma unroll
                for (int v = 0; v < 7; ++v) {
                    const ulonglong2 wv = *reinterpret_cast<const ulonglong2*>(
                        wb + v * EE + e);                       // LDS.128
#pragma unroll
                    for (int bb = 0; bb < 4; ++bb) {
                        ffma2(acc[bb][v], xv[bb].x, wv.x);
                        ffma2(acc[bb][v], xv[bb].y, wv.y);
                    }
                }
            }
        }
        __syncthreads();   // buffer (w&1) may be overwritten by stage(w+2)
    }

    // horizontal: packed halves, then warp butterfly
    float r[4][7];
#pragma unroll
    for (int bb = 0; bb < 4; ++bb)
#pragma unroll
        for (int v = 0; v < 7; ++v) {
            const float2 p = unpack2(acc[bb][v]);
            r[bb][v] = p.x + p.y;
        }
#pragma unroll
    for (int off = 16; off > 0; off >>= 1)
#pragma unroll
        for (int bb = 0; bb < 4; ++bb)
#pragma unroll
            for (int v = 0; v < 7; ++v)
                r[bb][v] += __shfl_xor_sync(0xffffffffu, r[bb][v], off);

    if (lane == 0) {
#pragma unroll
        for (int v = 0; v < 7; ++v) {
            const float bv = bias[t * WW + v];
#pragma unroll
            for (int bb = 0; bb < 4; ++bb) {
                const float z = r[bb][v] + bv;
                s_gates[(b0 + bb) * 8 + v] = 1.0f / (1.0f + __expf(-z));
            }
        }
    }
    __syncwarp();   // each warp only reads gates its own lane 0 wrote

    // ------------------------------------------------------------------
    // Step 2: out[b,t,e] = tanh( sum_w g[b][w] * x[b,t+w-3,e] )
    // ------------------------------------------------------------------
    unsigned long long gg[4][7];
#pragma unroll
    for (int bb = 0; bb < 4; ++bb)
#pragma unroll
        for (int v = 0; v < 7; ++v)
            gg[bb][v] = pack_dup(s_gates[(b0 + bb) * 8 + v]);

#pragma unroll
    for (int c = 0; c < 8; ++c) {
        const int e = (c << 7) + e0;
#pragma unroll
        for (int bb = 0; bb < 4; ++bb) {
            const float* xb = x + (size_t)(b0 + bb) * SS * EE + e;
            unsigned long long o0 = 0ull, o1 = 0ull;
#pragma unroll
            for (int w = 0; w < WW; ++w) {   // compile-time w -> no reg indexing
                if (w >= wlo && w < whi) {
                    const int row = t + w - HWD;
                    const ulonglong2 xv = *reinterpret_cast<const ulonglong2*>(
                        xb + (size_t)row * EE);
                    ffma2(o0, gg[bb][w], xv.x);
                    ffma2(o1, gg[bb][w], xv.y);
                }
            }
            const float2 p0 = unpack2(o0);
            const float2 p1 = unpack2(o1);
            float4 ov;
            ov.x = tanh_ap(p0.x);
            ov.y = tanh_ap(p0.y);
            ov.z = tanh_ap(p1.x);
            ov.w = tanh_ap(p1.y);
            *reinterpret_cast<float4*>(
                out + ((size_t)(b0 + bb) * SS + t) * EE + e) = ov;
        }
    }
}

extern "C" void kernel_launch(void* const* d_in, const int* in_sizes, int n_in,
                              void* d_out, int out_size) {
    const float* x    = (const float*)d_in[0];
    const float* wgt  = (const float*)d_in[1];
    const float* bias = (const float*)d_in[2];
    float* out        = (float*)d_out;

    static bool attr_set = false;
    if (!attr_set) {
        cudaFuncSetAttribute(soft_reorder_kernel,
                             cudaFuncAttributeMaxDynamicSharedMemorySize,
                             SMEM_BYTES);
        cudaFuncSetAttribute(soft_reorder_kernel,
                             cudaFuncAttributePreferredSharedMemoryCarveout,
                             100);
        attr_set = true;
    }
    soft_reorder_kernel<<<SS, 128, SMEM_BYTES>>>(x, wgt, bias, out);
}

// round 7
// speedup vs baseline: 1.5713x; 1.2912x over previous
#include <cuda_runtime.h>
#include <cstdint>

// SoftReordering, R6: T=2 t-blocking.
//   CTA owns (t0, t0+1). Iterates shared x rows r = t0-3+i, i in 0..7.
//   Row r is window tap w0=i for t0 (valid i<7) and w1=i-1 for t1 (valid i>=1).
//   x row is loaded ONCE per warp and feeds both t's accumulators -> x L2
//   traffic halves vs. 1-CTA-per-t. Weight slabs (14 v-rows x 512 floats)
//   staged via cp.async, double-buffered. Gates stay in registers.

#define SSEQ 1024
#define EE   1024
#define WW   7
#define WE   7168                 // W*E
#define HALF 512                  // e-half chunk (floats)
#define SLABF (14 * HALF)         // floats per slab = 7168 (28KB)
#define SMEM_BYTES (2 * SLABF * 4)  // 57344

__device__ __forceinline__ uint32_t smem_u32(const void* p) {
    uint32_t a;
    asm("{ .reg .u64 t; cvta.to.shared.u64 t, %1; cvt.u32.u64 %0, t; }"
        : "=r"(a) : "l"(p));
    return a;
}
__device__ __forceinline__ void cp_async16(uint32_t saddr, const void* gptr) {
    asm volatile("cp.async.cg.shared.global [%0], [%1], 16;"
                 :: "r"(saddr), "l"(gptr));
}
__device__ __forceinline__ void cp_commit() {
    asm volatile("cp.async.commit_group;");
}
template <int N>
__device__ __forceinline__ void cp_wait() {
    asm volatile("cp.async.wait_group %0;" :: "n"(N));
}
__device__ __forceinline__ void ffma2(unsigned long long& d,
                                      unsigned long long a,
                                      unsigned long long b) {
    asm("fma.rn.f32x2 %0, %1, %2, %3;" : "=l"(d) : "l"(a), "l"(b), "l"(d));
}
__device__ __forceinline__ float2 unpack2(unsigned long long v) {
    float2 r;
    asm("mov.b64 {%0, %1}, %2;" : "=f"(r.x), "=f"(r.y) : "l"(v));
    return r;
}
__device__ __forceinline__ unsigned long long pack_dup(float g) {
    unsigned long long p;
    asm("mov.b64 %0, {%1, %1};" : "=l"(p) : "f"(g));
    return p;
}
__device__ __forceinline__ float tanh_ap(float x) {
    float r;
    asm("tanh.approx.f32 %0, %1;" : "=f"(r) : "f"(x));
    return r;
}

__global__ void __launch_bounds__(256, 2)
soft_reorder_kernel(const float* __restrict__ x,
                    const float* __restrict__ wgt,
                    const float* __restrict__ bias,
                    float* __restrict__ out) {
    extern __shared__ float smem[];
    const int t0   = (int)blockIdx.x * 2;
    const int t1   = t0 + 1;
    const int tid  = threadIdx.x;
    const int lane = tid & 31;
    const int warp = tid >> 5;
    const int b0   = warp << 1;            // warp owns batches b0, b0+1
    const uint32_t sbase = smem_u32(smem);

    // Stage slab for phase p = i*2 + h (row-iter i, e-half h) into buffer buf.
    // Slab layout [14][HALF]: rows 0-6 = weight[t0, v, i*E + h*HALF + :],
    //                         rows 7-13 = weight[t1, v, (i-1)*E + h*HALF + :].
    auto stage = [&](int p, int buf) {
        const int i = p >> 1, h = p & 1;
        const int r = t0 - 3 + i;
        if (r >= 0 && r < SSEQ) {
            const uint32_t dst = sbase + (uint32_t)buf * (SLABF * 4);
#pragma unroll
            for (int k = 0; k < 7; ++k) {
                const int j   = tid + (k << 8);     // 0..1791
                const int row = j >> 7;             // 0..13 (uniform per warp)
                const int col = (j & 127) << 2;     // float offset in half-row
                const float* src;
                bool ok;
                if (row < 7) {
                    ok  = (i < 7);
                    src = wgt + (size_t)(t0 * WW + row) * WE
                              + (size_t)i * EE + h * HALF + col;
                } else {
                    ok  = (i >= 1);
                    src = wgt + (size_t)(t1 * WW + (row - 7)) * WE
                              + (size_t)(i - 1) * EE + h * HALF + col;
                }
                if (ok)
                    cp_async16(dst + (uint32_t)(row * HALF + col) * 4, src);
            }
        }
        cp_commit();
    };

    // ------------------------------------------------------------------
    // Step 1: logits for both t's, warp's 2 batches.  acc[tt][v][bb] (f32x2).
    // ------------------------------------------------------------------
    unsigned long long acc[2][7][2];
#pragma unroll
    for (int tt = 0; tt < 2; ++tt)
#pragma unroll
        for (int v = 0; v < 7; ++v)
#pragma unroll
            for (int bb = 0; bb < 2; ++bb)
                acc[tt][v][bb] = 0ull;

    stage(0, 0);
    for (int p = 0; p < 16; ++p) {
        if (p < 15) { stage(p + 1, (p + 1) & 1); cp_wait<1>(); }
        else        { cp_wait<0>(); }
        __syncthreads();

        const int i = p >> 1, h = p & 1;
        const int r = t0 - 3 + i;
        if (r >= 0 && r < SSEQ) {
            const float* xr = x + ((size_t)b0 * SSEQ + r) * EE + h * HALF;
            const float* wb = smem + (p & 1) * SLABF;
            const bool v0 = (i < 7), v1 = (i >= 1);
#pragma unroll
            for (int c = 0; c < 4; ++c) {
                const int el = (c << 7) + (lane << 2);
                const ulonglong2 xA = *reinterpret_cast<const ulonglong2*>(xr + el);
                const ulonglong2 xB = *reinterpret_cast<const ulonglong2*>(
                    xr + (size_t)SSEQ * EE + el);
                if (v0) {
#pragma unroll
                    for (int v = 0; v < 7; ++v) {
                        const ulonglong2 wv = *reinterpret_cast<const ulonglong2*>(
                            wb + v * HALF + el);
                        ffma2(acc[0][v][0], xA.x, wv.x);
                        ffma2(acc[0][v][0], xA.y, wv.y);
                        ffma2(acc[0][v][1], xB.x, wv.x);
                        ffma2(acc[0][v][1], xB.y, wv.y);
                    }
                }
                if (v1) {
#pragma unroll
                    for (int v = 0; v < 7; ++v) {
                        const ulonglong2 wv = *reinterpret_cast<const ulonglong2*>(
                            wb + (7 + v) * HALF + el);
                        ffma2(acc[1][v][0], xA.x, wv.x);
                        ffma2(acc[1][v][0], xA.y, wv.y);
                        ffma2(acc[1][v][1], xB.x, wv.x);
                        ffma2(acc[1][v][1], xB.y, wv.y);
                    }
                }
            }
        }
        __syncthreads();   // buffer (p&1) is restaged at p+2
    }

    // Reduce over lanes; gates stay in registers (all lanes hold the sums).
    unsigned long long gg[2][7][2];
#pragma unroll
    for (int tt = 0; tt < 2; ++tt)
#pragma unroll
        for (int v = 0; v < 7; ++v) {
            const float bz = bias[(tt ? t1 : t0) * WW + v];
#pragma unroll
            for (int bb = 0; bb < 2; ++bb) {
                const float2 q = unpack2(acc[tt][v][bb]);
                float s = q.x + q.y;
#pragma unroll
                for (int o = 16; o > 0; o >>= 1)
                    s += __shfl_xor_sync(0xffffffffu, s, o);
                const float z = s + bz;
                const float gs = 1.0f / (1.0f + __expf(-z));
                gg[tt][v][bb] = pack_dup(gs);
            }
        }

    // ------------------------------------------------------------------
    // Step 2: out[b, t, e] = tanh( sum_w g * x[b, t+w-3, e] ), both t's.
    // Row r feeds t0 with gg[0][i] (i<7) and t1 with gg[1][i-1] (i>=1).
    // ------------------------------------------------------------------
#pragma unroll
    for (int c = 0; c < 8; ++c) {
        const int e = (c << 7) + (lane << 2);
        const float* xe = x + (size_t)b0 * SSEQ * EE + e;
        unsigned long long o[2][2][2];
#pragma unroll
        for (int tt = 0; tt < 2; ++tt)
#pragma unroll
            for (int bb = 0; bb < 2; ++bb) {
                o[tt][bb][0] = 0ull; o[tt][bb][1] = 0ull;
            }
#pragma unroll
        for (int i = 0; i < 8; ++i) {
            const int r = t0 - 3 + i;
            if (r >= 0 && r < SSEQ) {
                const ulonglong2 xA = *reinterpret_cast<const ulonglong2*>(
                    xe + (size_t)r * EE);
                const ulonglong2 xB = *reinterpret_cast<const ulonglong2*>(
                    xe + (size_t)(SSEQ + r) * EE);
                if (i < 7) {
                    ffma2(o[0][0][0], gg[0][i][0], xA.x);
                    ffma2(o[0][0][1], gg[0][i][0], xA.y);
                    ffma2(o[0][1][0], gg[0][i][1], xB.x);
                    ffma2(o[0][1][1], gg[0][i][1], xB.y);
                }
                if (i >= 1) {
                    ffma2(o[1][0][0], gg[1][i - 1][0], xA.x);
                    ffma2(o[1][0][1], gg[1][i - 1][0], xA.y);
                    ffma2(o[1][1][0], gg[1][i - 1][1], xB.x);
                    ffma2(o[1][1][1], gg[1][i - 1][1], xB.y);
                }
            }
        }
#pragma unroll
        for (int tt = 0; tt < 2; ++tt)
#pragma unroll
            for (int bb = 0; bb < 2; ++bb) {
                const float2 p0 = unpack2(o[tt][bb][0]);
                const float2 p1 = unpack2(o[tt][bb][1]);
                float4 ov;
                ov.x = tanh_ap(p0.x);
                ov.y = tanh_ap(p0.y);
                ov.z = tanh_ap(p1.x);
                ov.w = tanh_ap(p1.y);
                *reinterpret_cast<float4*>(
                    out + ((size_t)(b0 + bb) * SSEQ + (tt ? t1 : t0)) * EE + e) = ov;
            }
    }
}

extern "C" void kernel_launch(void* const* d_in, const int* in_sizes, int n_in,
                              void* d_out, int out_size) {
    const float* x    = (const float*)d_in[0];
    const float* wgt  = (const float*)d_in[1];
    const float* bias = (const float*)d_in[2];
    float* out        = (float*)d_out;

    static bool attr_set = false;
    if (!attr_set) {
        cudaFuncSetAttribute(soft_reorder_kernel,
                             cudaFuncAttributeMaxDynamicSharedMemorySize,
                             SMEM_BYTES);
        attr_set = true;
    }
    soft_reorder_kernel<<<SSEQ / 2, 256, SMEM_BYTES>>>(x, wgt, bias, out);
}